// round 6
// baseline (speedup 1.0000x reference)
#include <cuda_runtime.h>
#include <cuda_bf16.h>
#include <cstdint>

// Problem shapes (fixed by the dataset)
#define S_LEN 2048
#define BATCH 16
#define DDIM  2048

// Stage-1 tiling
#define OTILE   128                 // output rows per block
#define KSPLIT  16
#define KCHUNK  (DDIM / KSPLIT)     // 128 d per block
#define SUBK    32                  // d per pipelined sub-chunk
#define NSUB    (KCHUNK / SUBK)     // 4
#define WROWPAD 33                  // sW bank = (t + d) % 32 -> conflict-free
#define SPAD    20                  // sS row stride: 80B, 16B-aligned LDS.128

// Scratch (device globals: allocation-free).
// g_part layout: [kc][o][b] -> thread stores 16 consecutive floats.
__device__ float g_part[KSPLIT * DDIM * BATCH];   // 2 MB
__device__ float g_altered[BATCH * DDIM];         // [b][o], 128 KB

__device__ __forceinline__ void ffma2(uint64_t& d, uint64_t a, uint64_t b) {
    asm("fma.rn.f32x2 %0, %1, %2, %0;" : "+l"(d) : "l"(a), "l"(b));
}

// ---------------------------------------------------------------------------
// Kernel 1a: partial[kc][o][b] = sum_{d in 128-chunk kc} state[b][d] * W[o][d]
// 256 blocks (~2 waves). Software pipeline: while computing sub-chunk c from
// smem, the W tile for c+1 is in flight in registers (8 LDG.128, coalesced,
// nL=4). Double-buffered sW -> one __syncthreads per sub-chunk. state staged
// once (sS[d][20], broadcast LDS.128 reads). 8 packed FFMA2 per d per thread.
// ---------------------------------------------------------------------------
__global__ void __launch_bounds__(128)
stage1_part(const float* __restrict__ state,
            const float* __restrict__ W)
{
    __shared__ float sW[2][OTILE][WROWPAD];   // 33 KB
    __shared__ float sS[KCHUNK][SPAD];        // 10 KB

    const int t     = threadIdx.x;            // 0..127 = local o
    const int obase = blockIdx.x * OTILE;
    const int kc    = blockIdx.y;
    const int d0    = kc * KCHUNK;

    // W load geometry (per sub-chunk): 8 float4/thread, coalesced.
    const int r  = ((t & 127) >> 3);          // base row contribution via j
    const int c4 = t & 7;                     // float4 column within 32-d row
    (void)r;

    // --- Prologue: state chunk to regs (16 coalesced scalar LDG, MLP=16)
    float sv[BATCH];
#pragma unroll
    for (int b = 0; b < BATCH; ++b)
        sv[b] = state[b * DDIM + d0 + t];

    // --- Prefetch W sub-chunk 0 into regs (8 independent LDG.128)
    float4 wreg[8];
#pragma unroll
    for (int j = 0; j < 8; ++j) {
        const int row = 16 * j + (t >> 3);
        wreg[j] = *(const float4*)(W + (long)(obase + row) * DDIM + d0 + c4 * 4);
    }

    // --- Stage state (bank 4-way conflicts, prologue-only)
#pragma unroll
    for (int b = 0; b < BATCH; ++b)
        sS[t][b] = sv[b];

    // --- Stage W sub-chunk 0 (conflict-free scalar STS: bank (row+4c4+k)%32)
#pragma unroll
    for (int j = 0; j < 8; ++j) {
        const int row = 16 * j + (t >> 3);
        sW[0][row][c4 * 4 + 0] = wreg[j].x;
        sW[0][row][c4 * 4 + 1] = wreg[j].y;
        sW[0][row][c4 * 4 + 2] = wreg[j].z;
        sW[0][row][c4 * 4 + 3] = wreg[j].w;
    }
    __syncthreads();

    uint64_t acc[8];
#pragma unroll
    for (int i = 0; i < 8; ++i) acc[i] = 0ull;

#pragma unroll
    for (int c = 0; c < NSUB; ++c) {
        // Prefetch next sub-chunk while computing this one.
        if (c < NSUB - 1) {
#pragma unroll
            for (int j = 0; j < 8; ++j) {
                const int row = 16 * j + (t >> 3);
                wreg[j] = *(const float4*)(W + (long)(obase + row) * DDIM
                                           + d0 + (c + 1) * SUBK + c4 * 4);
            }
        }

        const int buf = c & 1;
#pragma unroll
        for (int dd = 0; dd < SUBK; ++dd) {
            const float w = sW[buf][t][dd];            // bank (t+dd)%32
            uint64_t wp;
            asm("mov.b64 %0, {%1, %1};" : "=l"(wp) : "r"(__float_as_uint(w)));
            const int dl = c * SUBK + dd;
            const ulonglong2 q0 = *(const ulonglong2*)&sS[dl][0];   // broadcast
            const ulonglong2 q1 = *(const ulonglong2*)&sS[dl][4];
            const ulonglong2 q2 = *(const ulonglong2*)&sS[dl][8];
            const ulonglong2 q3 = *(const ulonglong2*)&sS[dl][12];
            ffma2(acc[0], wp, q0.x);  ffma2(acc[1], wp, q0.y);
            ffma2(acc[2], wp, q1.x);  ffma2(acc[3], wp, q1.y);
            ffma2(acc[4], wp, q2.x);  ffma2(acc[5], wp, q2.y);
            ffma2(acc[6], wp, q3.x);  ffma2(acc[7], wp, q3.y);
        }

        if (c < NSUB - 1) {
            const int nbuf = (c + 1) & 1;
#pragma unroll
            for (int j = 0; j < 8; ++j) {
                const int row = 16 * j + (t >> 3);
                sW[nbuf][row][c4 * 4 + 0] = wreg[j].x;
                sW[nbuf][row][c4 * 4 + 1] = wreg[j].y;
                sW[nbuf][row][c4 * 4 + 2] = wreg[j].z;
                sW[nbuf][row][c4 * 4 + 3] = wreg[j].w;
            }
            __syncthreads();
        }
    }

    // Unpack 8 x f32x2 -> 16 floats, 4 STG.128 (coalesced-ish, tiny traffic).
    float res[16];
#pragma unroll
    for (int i = 0; i < 8; ++i)
        asm("mov.b64 {%0, %1}, %2;" : "=f"(res[2 * i]), "=f"(res[2 * i + 1]) : "l"(acc[i]));

    float* dst = g_part + ((long)kc * DDIM + (obase + t)) * BATCH;
#pragma unroll
    for (int i = 0; i < 4; ++i)
        *(float4*)(dst + i * 4) =
            make_float4(res[i * 4], res[i * 4 + 1], res[i * 4 + 2], res[i * 4 + 3]);
}

// ---------------------------------------------------------------------------
// Kernel 1b: altered[b][o] = bias[o] + sum_kc partial[kc][o][b]
// ---------------------------------------------------------------------------
__global__ void __launch_bounds__(256)
stage1_reduce(const float* __restrict__ bias)
{
    const int n = blockIdx.x * 256 + threadIdx.x;   // 0..32767
    const int o = n >> 4;
    const int b = n & 15;
    float v = bias[o];
#pragma unroll
    for (int kc = 0; kc < KSPLIT; ++kc)
        v += g_part[(long)kc * DDIM * BATCH + n];
    g_altered[b * DDIM + o] = v;
}

// ---------------------------------------------------------------------------
// Kernel 2: weights[b][s] = sum_d altered[b][d] * enc[s][b][d]
// At the LTS chip cap (~6.3 TB/s) -- unchanged.
// ---------------------------------------------------------------------------
__global__ void __launch_bounds__(256, 8)
stage2_dots(const float* __restrict__ enc,
            float* __restrict__ out)
{
    __shared__ float alt[DDIM];

    const int tid    = threadIdx.x;
    const int warpId = tid >> 5;
    const int lane   = tid & 31;
    const int b      = blockIdx.y;
    const int s      = blockIdx.x * 8 + warpId;

#pragma unroll
    for (int j = 0; j < 2; ++j) {
        int f4 = tid + j * 256;
        *(float4*)&alt[f4 * 4] = *(const float4*)(g_altered + b * DDIM + f4 * 4);
    }
    __syncthreads();

    const float* row = enc + ((long)s * BATCH + b) * DDIM;

    float4 acc = make_float4(0.f, 0.f, 0.f, 0.f);
#pragma unroll
    for (int i = 0; i < 16; ++i) {
        const int d = i * 128 + lane * 4;
        const float4 e = *(const float4*)(row + d);
        const float4 a = *(const float4*)&alt[d];
        acc.x += e.x * a.x;
        acc.y += e.y * a.y;
        acc.z += e.z * a.z;
        acc.w += e.w * a.w;
    }

    float tt = (acc.x + acc.y) + (acc.z + acc.w);
#pragma unroll
    for (int off = 16; off > 0; off >>= 1)
        tt += __shfl_down_sync(0xFFFFFFFFu, tt, off);

    if (lane == 0)
        out[b * S_LEN + s] = tt;   // output shape [B, S]
}

extern "C" void kernel_launch(void* const* d_in, const int* in_sizes, int n_in,
                              void* d_out, int out_size)
{
    const float* enc   = (const float*)d_in[0];  // [S, B, D]
    const float* state = (const float*)d_in[1];  // [B, D]
    const float* W     = (const float*)d_in[2];  // [D, D]
    const float* bias  = (const float*)d_in[3];  // [D]
    float* out         = (float*)d_out;          // [B, S]

    stage1_part<<<dim3(DDIM / OTILE, KSPLIT), 128>>>(state, W);
    stage1_reduce<<<(BATCH * DDIM) / 256, 256>>>(bias);
    stage2_dots<<<dim3(S_LEN / 8, BATCH), 256>>>(enc, out);
}